// round 6
// baseline (speedup 1.0000x reference)
#include <cuda_runtime.h>
#include <cstdint>

#define N_NODES   100000
#define N_EDGES   640000
#define IN_FEAT   128
#define HALF_N    50000              // nodes per smem phase
#define SMEM_BYTES (HALF_N * 4)      // 195.3 KB

#define SCORE_SCALE     2048.0f      // 2^11 fixed point
#define SCORE_INV_SCALE (1.0f / 2048.0f)

#define EDGE_BLOCKS   96
#define EDGE_THREADS  1024
#define EDGE_STRIDE   (EDGE_BLOCKS * EDGE_THREADS)   // 98304
#define EDGES_PER_THR 7                               // 98304*7 = 688128 >= 640000

// Packed per-node scores: low int16 = src score, high int16 = trg score.
__device__ int g_score[N_NODES];

// ---------------------------------------------------------------------------
// Kernel 1: per-node dual dot products, 2 nodes per warp (best config).
// ---------------------------------------------------------------------------
__global__ __launch_bounds__(512) void node_scores_kernel(
    const float* __restrict__ x,     // [N_NODES, 128]
    const float* __restrict__ W)     // [1, 256] = [W_src(128) | W_trg(128)]
{
    const int warp_in_block = threadIdx.x >> 5;
    const int lane          = threadIdx.x & 31;
    const int w     = blockIdx.x * 16 + warp_in_block;
    const int nodeA = 2 * w;
    const int nodeB = 2 * w + 1;
    if (nodeA >= N_NODES) return;

    const float4 ws = __ldg(reinterpret_cast<const float4*>(W)           + lane);
    const float4 wt = __ldg(reinterpret_cast<const float4*>(W + IN_FEAT) + lane);

    const float4 xa = __ldg(reinterpret_cast<const float4*>(x + (size_t)nodeA * IN_FEAT) + lane);
    const float4 xb = __ldg(reinterpret_cast<const float4*>(x + (size_t)nodeB * IN_FEAT) + lane);

    float ssA = xa.x * ws.x + xa.y * ws.y + xa.z * ws.z + xa.w * ws.w;
    float stA = xa.x * wt.x + xa.y * wt.y + xa.z * wt.z + xa.w * wt.w;
    float ssB = xb.x * ws.x + xb.y * ws.y + xb.z * ws.z + xb.w * ws.w;
    float stB = xb.x * wt.x + xb.y * wt.y + xb.z * wt.z + xb.w * wt.w;

    #pragma unroll
    for (int off = 16; off > 0; off >>= 1) {
        ssA += __shfl_xor_sync(0xFFFFFFFFu, ssA, off);
        stA += __shfl_xor_sync(0xFFFFFFFFu, stA, off);
        ssB += __shfl_xor_sync(0xFFFFFFFFu, ssB, off);
        stB += __shfl_xor_sync(0xFFFFFFFFu, stB, off);
    }
    if (lane == 0) {
        int sa = __float2int_rn(fminf(fmaxf(ssA * SCORE_SCALE, -32767.0f), 32767.0f));
        int ta = __float2int_rn(fminf(fmaxf(stA * SCORE_SCALE, -32767.0f), 32767.0f));
        int sb = __float2int_rn(fminf(fmaxf(ssB * SCORE_SCALE, -32767.0f), 32767.0f));
        int tb = __float2int_rn(fminf(fmaxf(stB * SCORE_SCALE, -32767.0f), 32767.0f));
        g_score[nodeA] = (sa & 0xFFFF) | (ta << 16);
        g_score[nodeB] = (sb & 0xFFFF) | (tb << 16);
    }
}

// ---------------------------------------------------------------------------
// Kernel 2: smem-staged gather. Two phases; each phase stages half the packed
// score table (195KB) into shared memory, then every thread resolves the
// endpoints of its 7 register-held edges that fall in that node range via
// random LDS (no L1tex wavefront-replay penalty). Coalesced index loads and
// coalesced output stores (grid-stride edge assignment).
// ---------------------------------------------------------------------------
__global__ __launch_bounds__(EDGE_THREADS) void edge_sigmoid_smem_kernel(
    const int*   __restrict__ edge_src,
    const int*   __restrict__ edge_trg,
    const float* __restrict__ b,
    float*       __restrict__ out)
{
    extern __shared__ int sh[];   // HALF_N packed scores

    const int tid0 = blockIdx.x * EDGE_THREADS + threadIdx.x;

    // Load this thread's edge indices (coalesced), keep in registers.
    int s[EDGES_PER_THR], t[EDGES_PER_THR], acc[EDGES_PER_THR];
    #pragma unroll
    for (int i = 0; i < EDGES_PER_THR; ++i) {
        const int e = tid0 + i * EDGE_STRIDE;
        const bool v = (e < N_EDGES);
        s[i]   = v ? __ldg(edge_src + e) : 0;
        t[i]   = v ? __ldg(edge_trg + e) : 0;
        acc[i] = 0;
    }

    #pragma unroll
    for (int ph = 0; ph < 2; ++ph) {
        const int lo = ph * HALF_N;
        if (ph) __syncthreads();          // protect smem from prior readers

        // Populate: 12500 int4 = 195KB, coalesced, high MLP.
        {
            const int4* src = reinterpret_cast<const int4*>(g_score + lo);
            int4*       dst = reinterpret_cast<int4*>(sh);
            for (int j = threadIdx.x; j < HALF_N / 4; j += EDGE_THREADS)
                dst[j] = __ldg(src + j);
        }
        __syncthreads();

        // Gather from smem for endpoints in [lo, lo+HALF_N).
        #pragma unroll
        for (int i = 0; i < EDGES_PER_THR; ++i) {
            const unsigned us = (unsigned)(s[i] - lo);
            if (us < (unsigned)HALF_N) acc[i] += (int)(short)(sh[us] & 0xFFFF);
            const unsigned ut = (unsigned)(t[i] - lo);
            if (ut < (unsigned)HALF_N) acc[i] += (sh[ut] >> 16);
        }
    }

    const float bias = __ldg(b);
    #pragma unroll
    for (int i = 0; i < EDGES_PER_THR; ++i) {
        const int e = tid0 + i * EDGE_STRIDE;
        if (e < N_EDGES) {
            const float z = (float)acc[i] * SCORE_INV_SCALE + bias;
            out[e] = 1.0f / (1.0f + __expf(-z));
        }
    }
}

// ---------------------------------------------------------------------------
extern "C" void kernel_launch(void* const* d_in, const int* in_sizes, int n_in,
                              void* d_out, int out_size)
{
    // Identify inputs defensively by element count.
    const float* x  = nullptr;
    const int*   es = nullptr;
    const int*   et = nullptr;
    const float* W  = nullptr;
    const float* b  = nullptr;

    for (int i = 0; i < n_in; ++i) {
        const int n = in_sizes[i];
        if (n == N_NODES * IN_FEAT)      x = (const float*)d_in[i];
        else if (n == N_EDGES) {
            if (!es) es = (const int*)d_in[i];
            else     et = (const int*)d_in[i];
        }
        else if (n == 2 * IN_FEAT)       W = (const float*)d_in[i];
        else if (n == 1)                 b = (const float*)d_in[i];
    }

    float* out = (float*)d_out;

    // Allow 195KB dynamic smem (idempotent; host-side attr set, not an alloc).
    static bool attr_done = false;
    if (!attr_done) {
        cudaFuncSetAttribute(edge_sigmoid_smem_kernel,
                             cudaFuncAttributeMaxDynamicSharedMemorySize,
                             SMEM_BYTES);
        attr_done = true;
    }

    // Kernel 1: 16 warps/block, 2 nodes/warp -> 32 nodes/block
    const int blocks1 = (N_NODES + 31) / 32;
    node_scores_kernel<<<blocks1, 512>>>(x, W);

    // Kernel 2: smem-staged edge pass.
    edge_sigmoid_smem_kernel<<<EDGE_BLOCKS, EDGE_THREADS, SMEM_BYTES>>>(es, et, b, out);
}

// round 7
// speedup vs baseline: 1.1064x; 1.1064x over previous
#include <cuda_runtime.h>
#include <cstdint>

#define N_NODES   100000
#define N_EDGES   640000
#define IN_FEAT   128

#define SCORE_SCALE     2048.0f      // 2^11 fixed point
#define SCORE_INV_SCALE (1.0f / 2048.0f)

// Packed per-node scores: low int16 = src score, high int16 = trg score.
__device__ int g_score[N_NODES];

// ---------------------------------------------------------------------------
// Kernel 1: per-node dual dot products, split-warp reduction.
// 2 nodes per warp: lanes 0-15 -> node A, lanes 16-31 -> node B.
// Each lane loads 2 float4s of its node's row (MLP=2, two aligned 256B
// segments per node). Butterfly reduction over 16 lanes: 4 stages x 2 values
// = 8 SHFL per 2 nodes (was 20).
// ---------------------------------------------------------------------------
__global__ __launch_bounds__(512) void node_scores_kernel(
    const float* __restrict__ x,     // [N_NODES, 128]
    const float* __restrict__ W)     // [1, 256] = [W_src(128) | W_trg(128)]
{
    const int warp_in_block = threadIdx.x >> 5;
    const int lane          = threadIdx.x & 31;
    const int half          = lane >> 4;        // 0: node A, 1: node B
    const int sub           = lane & 15;        // float4 slot within half-row

    const int w    = blockIdx.x * 16 + warp_in_block;
    const int node = 2 * w + half;
    if (2 * w >= N_NODES) return;               // N_NODES even -> both valid

    const float4* xr = reinterpret_cast<const float4*>(x + (size_t)node * IN_FEAT);
    const float4* w4 = reinterpret_cast<const float4*>(W);

    // Two independent row loads (slots sub and sub+16)
    const float4 x0 = __ldg(xr + sub);
    const float4 x1 = __ldg(xr + sub + 16);
    const float4 ws0 = __ldg(w4 + sub);
    const float4 ws1 = __ldg(w4 + sub + 16);
    const float4 wt0 = __ldg(w4 + 32 + sub);
    const float4 wt1 = __ldg(w4 + 32 + sub + 16);

    float ss = x0.x * ws0.x + x0.y * ws0.y + x0.z * ws0.z + x0.w * ws0.w
             + x1.x * ws1.x + x1.y * ws1.y + x1.z * ws1.z + x1.w * ws1.w;
    float st = x0.x * wt0.x + x0.y * wt0.y + x0.z * wt0.z + x0.w * wt0.w
             + x1.x * wt1.x + x1.y * wt1.y + x1.z * wt1.z + x1.w * wt1.w;

    // Butterfly over the 16-lane half-warp (xor offsets stay within halves)
    #pragma unroll
    for (int off = 8; off > 0; off >>= 1) {
        ss += __shfl_xor_sync(0xFFFFFFFFu, ss, off);
        st += __shfl_xor_sync(0xFFFFFFFFu, st, off);
    }

    if (sub == 0) {   // lanes 0 and 16 write their node
        int si = __float2int_rn(fminf(fmaxf(ss * SCORE_SCALE, -32767.0f), 32767.0f));
        int ti = __float2int_rn(fminf(fmaxf(st * SCORE_SCALE, -32767.0f), 32767.0f));
        g_score[node] = (si & 0xFFFF) | (ti << 16);
    }
}

// ---------------------------------------------------------------------------
// Kernel 2 (R5 winner): per-edge gather + sigmoid, 4 edges per thread.
// Two random 4B gathers per edge into ONE 400KB packed table.
// ---------------------------------------------------------------------------
__global__ __launch_bounds__(256) void edge_sigmoid_kernel(
    const int*   __restrict__ edge_src,
    const int*   __restrict__ edge_trg,
    const float* __restrict__ b,
    float*       __restrict__ out)
{
    const int g = blockIdx.x * blockDim.x + threadIdx.x;   // group of 4 edges
    if (g * 4 >= N_EDGES) return;

    const float bias = __ldg(b);

    const int4 s4 = __ldg(reinterpret_cast<const int4*>(edge_src) + g);
    const int4 t4 = __ldg(reinterpret_cast<const int4*>(edge_trg) + g);

    // Issue all 8 gathers before consuming.
    const int ps0 = g_score[s4.x], ps1 = g_score[s4.y];
    const int ps2 = g_score[s4.z], ps3 = g_score[s4.w];
    const int pt0 = g_score[t4.x], pt1 = g_score[t4.y];
    const int pt2 = g_score[t4.z], pt3 = g_score[t4.w];

    float4 r;
    {
        float z;
        z = (float)((short)ps0 + (pt0 >> 16)) * SCORE_INV_SCALE + bias;
        r.x = 1.0f / (1.0f + __expf(-z));
        z = (float)((short)ps1 + (pt1 >> 16)) * SCORE_INV_SCALE + bias;
        r.y = 1.0f / (1.0f + __expf(-z));
        z = (float)((short)ps2 + (pt2 >> 16)) * SCORE_INV_SCALE + bias;
        r.z = 1.0f / (1.0f + __expf(-z));
        z = (float)((short)ps3 + (pt3 >> 16)) * SCORE_INV_SCALE + bias;
        r.w = 1.0f / (1.0f + __expf(-z));
    }
    reinterpret_cast<float4*>(out)[g] = r;
}

// ---------------------------------------------------------------------------
extern "C" void kernel_launch(void* const* d_in, const int* in_sizes, int n_in,
                              void* d_out, int out_size)
{
    // Identify inputs defensively by element count.
    const float* x  = nullptr;
    const int*   es = nullptr;
    const int*   et = nullptr;
    const float* W  = nullptr;
    const float* b  = nullptr;

    for (int i = 0; i < n_in; ++i) {
        const int n = in_sizes[i];
        if (n == N_NODES * IN_FEAT)      x = (const float*)d_in[i];
        else if (n == N_EDGES) {
            if (!es) es = (const int*)d_in[i];
            else     et = (const int*)d_in[i];
        }
        else if (n == 2 * IN_FEAT)       W = (const float*)d_in[i];
        else if (n == 1)                 b = (const float*)d_in[i];
    }

    float* out = (float*)d_out;

    // Kernel 1: 16 warps/block, 2 nodes/warp -> 32 nodes/block
    const int blocks1 = (N_NODES + 31) / 32;
    node_scores_kernel<<<blocks1, 512>>>(x, W);

    // Kernel 2: 4 edges per thread -> 160K threads
    const int threads2 = N_EDGES / 4;                 // divides exactly
    const int blocks2  = (threads2 + 255) / 256;
    edge_sigmoid_kernel<<<blocks2, 256>>>(es, et, b, out);
}